// round 1
// baseline (speedup 1.0000x reference)
#include <cuda_runtime.h>

// Problem shapes (fixed by reference setup_inputs)
#define B_  32
#define N_  6
#define D_  128
#define CHW 262144           // 256*32*32
#define CHW4 65536           // CHW/4 (float4)
#define OUT_MAIN 8388608     // B*CHW

// Scratch: attention weights per (b, n)
__device__ float g_w[B_ * N_];

// ---------------------------------------------------------------------------
// Kernel A: compute sparsemax attention weights.
// grid = 32 blocks (one per batch), 128 threads.
// Each block redundantly computes u_feat = W_out @ W_feat, u_ctx = W_out @ W_ctx
// (thread t owns column t; 2*128 FMAs/thread — negligible), then the 6 logits
// via block reduction, then thread 0 runs sparsemax over the 6 values.
// Also writes the second output (transposed attn): (B,N,1)->(B,1,N) is the
// identical flat layout, so it's just g_w flattened.
// ---------------------------------------------------------------------------
__global__ void __launch_bounds__(128, 1)
attn_weights_kernel(const float* __restrict__ q,
                    const float* __restrict__ k,
                    const float* __restrict__ W_feat,
                    const float* __restrict__ b_feat,
                    const float* __restrict__ W_ctx,
                    const float* __restrict__ b_ctx,
                    const float* __restrict__ W_out,
                    const float* __restrict__ b_out,
                    float* __restrict__ out_attn)
{
    const int b = blockIdx.x;
    const int t = threadIdx.x;          // 0..127
    const int lane = t & 31;
    const int warp = t >> 5;

    // u_feat[t], u_ctx[t]
    float uf = 0.f, uc = 0.f;
    #pragma unroll 8
    for (int e = 0; e < D_; e++) {
        const float wo = __ldg(&W_out[e]);
        uf = fmaf(wo, W_feat[e * D_ + t], uf);
        uc = fmaf(wo, W_ctx [e * D_ + t], uc);
    }

    __shared__ float sred[4];
    __shared__ float zsh[N_];
    __shared__ float csh;

    // constant c = W_out . (b_feat + b_ctx) + b_out
    {
        float cp = W_out[t] * (b_feat[t] + b_ctx[t]);
        #pragma unroll
        for (int off = 16; off; off >>= 1)
            cp += __shfl_down_sync(0xffffffffu, cp, off);
        if (lane == 0) sred[warp] = cp;
        __syncthreads();
        if (t == 0) csh = sred[0] + sred[1] + sred[2] + sred[3] + b_out[0];
        __syncthreads();
    }

    // logits z[n] = uf . k[b,n,:] + uc . q[b,n,:]
    for (int n = 0; n < N_; n++) {
        const float* kp = k + ((size_t)(b * N_ + n)) * D_;
        const float* qp = q + ((size_t)(b * N_ + n)) * D_;
        float p = fmaf(uf, kp[t], uc * qp[t]);
        #pragma unroll
        for (int off = 16; off; off >>= 1)
            p += __shfl_down_sync(0xffffffffu, p, off);
        if (lane == 0) sred[warp] = p;
        __syncthreads();
        if (t == 0) zsh[n] = sred[0] + sred[1] + sred[2] + sred[3];
        __syncthreads();
    }

    if (t == 0) {
        const float c = csh;
        float z[N_], zs[N_];
        #pragma unroll
        for (int n = 0; n < N_; n++) { z[n] = zsh[n] + c; zs[n] = z[n]; }

        // sort descending (insertion sort, K=6)
        #pragma unroll
        for (int i = 1; i < N_; i++) {
            float key = zs[i];
            int j = i - 1;
            while (j >= 0 && zs[j] < key) { zs[j + 1] = zs[j]; j--; }
            zs[j + 1] = key;
        }

        // sparsemax threshold
        float cs = 0.f, cs_k = 0.f;
        int   kk = 1;
        #pragma unroll
        for (int r = 1; r <= N_; r++) {
            cs += zs[r - 1];
            if (1.f + (float)r * zs[r - 1] > cs) { kk = r; cs_k = cs; }
        }
        const float tau = (cs_k - 1.f) / (float)kk;

        #pragma unroll
        for (int n = 0; n < N_; n++) {
            float w = z[n] - tau;
            w = w > 0.f ? w : 0.f;
            g_w[b * N_ + n]     = w;
            out_attn[b * N_ + n] = w;   // (B,1,N) flat == (B,N,1) flat
        }
    }
}

// ---------------------------------------------------------------------------
// Kernel B: out[b, chw] = sum_n w[b,n] * v[b, n, chw]   (float4 vectorized)
// grid = (CHW4/256, 32), block = 256. Weight-zero slices are skipped entirely
// (uniform predicate per block -> no divergence, no memory traffic for them).
// ---------------------------------------------------------------------------
__global__ void __launch_bounds__(256, 8)
wsum_kernel(const float* __restrict__ v, float* __restrict__ out)
{
    const int b = blockIdx.y;
    __shared__ float w[N_];
    if (threadIdx.x < N_) w[threadIdx.x] = g_w[b * N_ + threadIdx.x];
    __syncthreads();

    const size_t idx = (size_t)blockIdx.x * blockDim.x + threadIdx.x; // float4 idx in CHW4
    const float4* vb = reinterpret_cast<const float4*>(v) + (size_t)b * N_ * CHW4 + idx;

    float4 acc = make_float4(0.f, 0.f, 0.f, 0.f);
    #pragma unroll
    for (int n = 0; n < N_; n++) {
        const float wn = w[n];
        if (wn != 0.f) {                      // block-uniform: skips HBM read
            const float4 x = __ldg(vb + (size_t)n * CHW4);
            acc.x = fmaf(wn, x.x, acc.x);
            acc.y = fmaf(wn, x.y, acc.y);
            acc.z = fmaf(wn, x.z, acc.z);
            acc.w = fmaf(wn, x.w, acc.w);
        }
    }
    reinterpret_cast<float4*>(out)[(size_t)b * CHW4 + idx] = acc;
}

// ---------------------------------------------------------------------------
// Launch. Input order per setup_inputs: q, k, v, W_feat, b_feat, W_ctx,
// b_ctx, W_out, b_out. Output: [ (B,C,H,W) main | (B,1,N) attn ] fp32.
// ---------------------------------------------------------------------------
extern "C" void kernel_launch(void* const* d_in, const int* in_sizes, int n_in,
                              void* d_out, int out_size)
{
    const float* q      = (const float*)d_in[0];
    const float* k      = (const float*)d_in[1];
    const float* v      = (const float*)d_in[2];
    const float* W_feat = (const float*)d_in[3];
    const float* b_feat = (const float*)d_in[4];
    const float* W_ctx  = (const float*)d_in[5];
    const float* b_ctx  = (const float*)d_in[6];
    const float* W_out  = (const float*)d_in[7];
    const float* b_out  = (const float*)d_in[8];

    float* out      = (float*)d_out;
    float* out_attn = out + OUT_MAIN;

    attn_weights_kernel<<<B_, 128>>>(q, k, W_feat, b_feat, W_ctx, b_ctx,
                                     W_out, b_out, out_attn);
    wsum_kernel<<<dim3(CHW4 / 256, B_), 256>>>(v, out);
}

// round 4
// speedup vs baseline: 1.1159x; 1.1159x over previous
#include <cuda_runtime.h>

// Problem shapes (fixed by reference setup_inputs)
#define B_  32
#define N_  6
#define D_  128
#define CHW 262144           // 256*32*32
#define CHW4 65536           // CHW/4 (float4)
#define OUT_MAIN 8388608     // B*CHW

// Scratch: attention weights per (b, n)
__device__ float g_w[B_ * N_];

// ---------------------------------------------------------------------------
// Kernel A: ONE block, 1024 threads.
//  Phase 1: u_feat = W_out @ W_feat, u_ctx = W_out @ W_ctx  (batch-independent!)
//           8 segments of 128 threads; segment s sums 32 e-values for its half.
//  Phase 2: warp b (32 warps) computes the 6 logits for batch b.
//  Phase 3: lane 0 of warp b runs sparsemax over 6 values, writes g_w + attn out.
//  Then fence + PDL trigger so wsum can start as soon as g_w is visible.
// ---------------------------------------------------------------------------
__global__ void __launch_bounds__(1024, 1)
attn_weights_kernel(const float* __restrict__ q,
                    const float* __restrict__ k,
                    const float* __restrict__ W_feat,
                    const float* __restrict__ b_feat,
                    const float* __restrict__ W_ctx,
                    const float* __restrict__ b_ctx,
                    const float* __restrict__ W_out,
                    const float* __restrict__ b_out,
                    float* __restrict__ out_attn)
{
    __shared__ float s_part[8][128];
    __shared__ float s_uf[D_];
    __shared__ float s_uc[D_];
    __shared__ float s_c;

    const int tid  = threadIdx.x;
    const int col  = tid & 127;
    const int seg  = tid >> 7;            // 0..7

    // Phase 1: partial u sums. seg 0..3 -> u_feat, seg 4..7 -> u_ctx
    {
        const float* Wm = (seg < 4) ? W_feat : W_ctx;
        const int e0 = (seg & 3) * 32;
        float p = 0.f;
        #pragma unroll
        for (int i = 0; i < 32; i++) {
            const int e = e0 + i;
            p = fmaf(__ldg(&W_out[e]), Wm[e * D_ + col], p);
        }
        s_part[seg][col] = p;
    }

    // Constant c = W_out . (b_feat + b_ctx) + b_out  (warp 8 = threads 256..287)
    if (tid >= 256 && tid < 288) {
        const int l = tid - 256;
        float cp = 0.f;
        #pragma unroll
        for (int j = 0; j < 4; j++) {
            const int d = l * 4 + j;
            cp = fmaf(W_out[d], b_feat[d] + b_ctx[d], cp);
        }
        #pragma unroll
        for (int off = 16; off; off >>= 1)
            cp += __shfl_down_sync(0xffffffffu, cp, off);
        if (l == 0) s_c = cp + b_out[0];
    }
    __syncthreads();

    if (tid < 128) {
        s_uf[tid] = s_part[0][tid] + s_part[1][tid] + s_part[2][tid] + s_part[3][tid];
        s_uc[tid] = s_part[4][tid] + s_part[5][tid] + s_part[6][tid] + s_part[7][tid];
    }
    __syncthreads();

    // Phase 2: warp b handles batch b
    const int wid  = tid >> 5;            // 0..31 == batch
    const int lane = tid & 31;
    const float* kb = k + (size_t)wid * N_ * D_;
    const float* qb = q + (size_t)wid * N_ * D_;

    float z[N_];
    #pragma unroll
    for (int n = 0; n < N_; n++) {
        float p = 0.f;
        #pragma unroll
        for (int j = 0; j < 4; j++) {
            const int d = lane + j * 32;
            p = fmaf(s_uf[d], kb[n * D_ + d], p);
            p = fmaf(s_uc[d], qb[n * D_ + d], p);
        }
        #pragma unroll
        for (int off = 16; off; off >>= 1)
            p += __shfl_down_sync(0xffffffffu, p, off);
        z[n] = p;                         // valid on lane 0
    }

    // Phase 3: sparsemax per batch on lane 0
    if (lane == 0) {
        const float c = s_c;
        float zs[N_];
        #pragma unroll
        for (int n = 0; n < N_; n++) { z[n] += c; zs[n] = z[n]; }

        // insertion sort, descending (K=6)
        #pragma unroll
        for (int i = 1; i < N_; i++) {
            float key = zs[i];
            int j = i - 1;
            while (j >= 0 && zs[j] < key) { zs[j + 1] = zs[j]; j--; }
            zs[j + 1] = key;
        }

        float cs = 0.f, cs_k = 0.f;
        int   kk = 1;
        #pragma unroll
        for (int r = 1; r <= N_; r++) {
            cs += zs[r - 1];
            if (1.f + (float)r * zs[r - 1] > cs) { kk = r; cs_k = cs; }
        }
        const float tau = (cs_k - 1.f) / (float)kk;

        #pragma unroll
        for (int n = 0; n < N_; n++) {
            float w = z[n] - tau;
            w = w > 0.f ? w : 0.f;
            g_w[wid * N_ + n]      = w;
            out_attn[wid * N_ + n] = w;   // (B,1,N) flat == (B,N,1) flat
        }
    }

    // Make g_w globally visible, then release the dependent wsum grid early.
    __threadfence();
    cudaTriggerProgrammaticLaunchCompletion();
}

// ---------------------------------------------------------------------------
// Kernel B: out[b, chw] = sum_n w[b,n] * v[b, n, chw]
// 2x float4 per thread (block covers 512 contiguous float4s -> 12-deep MLP).
// PDL: cudaGridDependencySynchronize before reading g_w so CTA setup overlaps
// the tail of kernel A. Zero-weight slices skip their HBM reads entirely
// (weight is block-uniform -> no divergence).
// ---------------------------------------------------------------------------
__global__ void __launch_bounds__(256, 6)
wsum_kernel(const float* __restrict__ v, float* __restrict__ out)
{
    const int b = blockIdx.y;
    __shared__ float w[8];

    cudaGridDependencySynchronize();       // PDL: wait for attn_weights_kernel

    if (threadIdx.x < N_) w[threadIdx.x] = g_w[b * N_ + threadIdx.x];
    __syncthreads();

    const size_t base = (size_t)blockIdx.x * 512 + threadIdx.x;   // float4 index
    const float4* vb = reinterpret_cast<const float4*>(v) + (size_t)b * N_ * CHW4;

    float4 a0 = make_float4(0.f, 0.f, 0.f, 0.f);
    float4 a1 = make_float4(0.f, 0.f, 0.f, 0.f);
    #pragma unroll
    for (int n = 0; n < N_; n++) {
        const float wn = w[n];
        if (wn != 0.f) {                    // block-uniform: skips the HBM read
            const float4 x0 = __ldg(vb + (size_t)n * CHW4 + base);
            const float4 x1 = __ldg(vb + (size_t)n * CHW4 + base + 256);
            a0.x = fmaf(wn, x0.x, a0.x);  a0.y = fmaf(wn, x0.y, a0.y);
            a0.z = fmaf(wn, x0.z, a0.z);  a0.w = fmaf(wn, x0.w, a0.w);
            a1.x = fmaf(wn, x1.x, a1.x);  a1.y = fmaf(wn, x1.y, a1.y);
            a1.z = fmaf(wn, x1.z, a1.z);  a1.w = fmaf(wn, x1.w, a1.w);
        }
    }
    float4* ob = reinterpret_cast<float4*>(out) + (size_t)b * CHW4;
    ob[base]       = a0;
    ob[base + 256] = a1;
}

// ---------------------------------------------------------------------------
// Launch. Input order per setup_inputs: q, k, v, W_feat, b_feat, W_ctx,
// b_ctx, W_out, b_out. Output: [ (B,C,H,W) main | (B,1,N) attn ] fp32.
// ---------------------------------------------------------------------------
extern "C" void kernel_launch(void* const* d_in, const int* in_sizes, int n_in,
                              void* d_out, int out_size)
{
    const float* q      = (const float*)d_in[0];
    const float* k      = (const float*)d_in[1];
    const float* v      = (const float*)d_in[2];
    const float* W_feat = (const float*)d_in[3];
    const float* b_feat = (const float*)d_in[4];
    const float* W_ctx  = (const float*)d_in[5];
    const float* b_ctx  = (const float*)d_in[6];
    const float* W_out  = (const float*)d_in[7];
    const float* b_out  = (const float*)d_in[8];

    float* out      = (float*)d_out;
    float* out_attn = out + OUT_MAIN;

    attn_weights_kernel<<<1, 1024>>>(q, k, W_feat, b_feat, W_ctx, b_ctx,
                                     W_out, b_out, out_attn);

    // wsum with programmatic dependent launch (overlaps CTA setup with A's tail)
    cudaLaunchConfig_t cfg = {};
    cfg.gridDim  = dim3(CHW4 / 512, B_, 1);
    cfg.blockDim = dim3(256, 1, 1);
    cfg.dynamicSmemBytes = 0;
    cfg.stream = 0;
    cudaLaunchAttribute attr[1];
    attr[0].id = cudaLaunchAttributeProgrammaticStreamSerialization;
    attr[0].val.programmaticStreamSerializationAllowed = 1;
    cfg.attrs = attr;
    cfg.numAttrs = 1;
    cudaLaunchKernelEx(&cfg, wsum_kernel, v, out);
}